// round 4
// baseline (speedup 1.0000x reference)
#include <cuda_runtime.h>
#include <math.h>
#include <stdint.h>

#define NSEQ   1024
#define XDIM   2048
#define NHEADS 16
#define KVH    2
#define GQH    8
#define DH     128
#define QKVW   2560      // 2048 + 256 + 256
#define CDIM   4096      // CMP_BLK * DH
#define SCALE  0.08838834764831845f
#define NEGBIG -1e10f

// ---------------- scratch (device globals; no runtime allocation) ----------------
__device__ __align__(128) float g_xn    [NSEQ*XDIM];
__device__ __align__(128) float g_qkv   [NSEQ*QKVW];
__device__ __align__(128) float g_f     [2*128*CDIM];
__device__ __align__(128) float g_hidden[2*128*CDIM];
__device__ __align__(128) float g_ckv   [256*DH];
__device__ __align__(128) float g_ckfull[KVH*65*DH];
__device__ __align__(128) float g_cvfull[KVH*65*DH];
__device__ __align__(128) float g_cmp   [NHEADS*NSEQ*DH];
__device__ __align__(128) float g_fine  [NHEADS*NSEQ*DH];
__device__ __align__(128) float g_slide [NHEADS*NSEQ*DH];
__device__ __align__(128) float g_qrope [NHEADS*NSEQ*DH];
__device__ __align__(128) float g_krope [KVH*NSEQ*DH];
__device__ __align__(128) float g_O1    [NSEQ*XDIM];
__device__ __align__(128) float g_ropetab[NSEQ*64*2];
__device__ __align__(128) float g_gpart [16*NSEQ*48];
__device__ int g_sel[KVH*NSEQ*5];

// ---------------- helpers ----------------
__device__ __forceinline__ float warp_sum(float v){
    #pragma unroll
    for (int o = 16; o > 0; o >>= 1) v += __shfl_xor_sync(0xffffffffu, v, o);
    return v;
}
__device__ __forceinline__ float warp_max(float v){
    #pragma unroll
    for (int o = 16; o > 0; o >>= 1) v = fmaxf(v, __shfl_xor_sync(0xffffffffu, v, o));
    return v;
}
__device__ __forceinline__ float tf32r(float x){
    unsigned r; asm("cvt.rna.tf32.f32 %0, %1;" : "=r"(r) : "f"(x));
    return __uint_as_float(r);
}
__device__ __forceinline__ void mma8(float* d, const unsigned* a, const unsigned* b){
    asm volatile("mma.sync.aligned.m16n8k8.row.col.f32.tf32.tf32.f32 "
        "{%0,%1,%2,%3},{%4,%5,%6,%7},{%8,%9},{%0,%1,%2,%3};"
        : "+f"(d[0]),"+f"(d[1]),"+f"(d[2]),"+f"(d[3])
        : "r"(a[0]),"r"(a[1]),"r"(a[2]),"r"(a[3]),"r"(b[0]),"r"(b[1]));
}

// ---------------- rmsnorm ----------------
__global__ void rmsnorm_kernel(const float* __restrict__ x, const float* __restrict__ g){
    int n = blockIdx.x, tid = threadIdx.x;
    const float4* row = (const float4*)(x + (size_t)n*XDIM);
    float s = 0.f;
    for (int i = tid; i < XDIM/4; i += 256){
        float4 v = row[i];
        s += v.x*v.x + v.y*v.y + v.z*v.z + v.w*v.w;
    }
    s = warp_sum(s);
    __shared__ float red[8];
    __shared__ float tot;
    if ((tid & 31) == 0) red[tid >> 5] = s;
    __syncthreads();
    if (tid < 32){
        float v = (tid < 8) ? red[tid] : 0.f;
        v = warp_sum(v);
        if (tid == 0) tot = rsqrtf(v / (float)XDIM + 1e-6f);
    }
    __syncthreads();
    float inv = tot;
    const float4* gg = (const float4*)g;
    float4* op = (float4*)(g_xn + (size_t)n*XDIM);
    for (int i = tid; i < XDIM/4; i += 256){
        float4 v = row[i], w = gg[i], o;
        o.x = v.x*inv*w.x; o.y = v.y*inv*w.y; o.z = v.z*inv*w.z; o.w = v.w*inv*w.w;
        op[i] = o;
    }
}

// ---------------- TF32 tensor-core GEMM, fragment-layout smem ----------------
// Block tile BM x 128, 8 warps as 2(M) x 4(N); warp tile (BM/2) x 32.
// k-step 8, double buffered. SPLIT: 3xTF32 near-fp32.
// Smem holds operands pre-permuted into m16n8k8 fragment layout:
//   A frag (16 rows x 8 k): lane l=(row&7)*4+(k&3), slot s=((row>>3)&1)+2*(k>>2)
//   B frag (8 k x 8 col):   lane l=(col&7)*4+(k&3), slot s=(k>>2)
template<int BM, bool SPLIT>
__global__ __launch_bounds__(256)
void tf32_gemm_frag(const float* __restrict__ A,
                    const float* __restrict__ B0, const float* __restrict__ B1,
                    const float* __restrict__ bias0, const float* __restrict__ bias1,
                    float* __restrict__ C,
                    int M, int N, int K, int relu, size_t sA, size_t sC){
    constexpr int MT = BM / 32;          // m16 tiles per warp
    const float* B    = blockIdx.z ? B1    : B0;
    const float* bias = blockIdx.z ? bias1 : bias0;
    A += (size_t)blockIdx.z * sA;
    C += (size_t)blockIdx.z * sC;

    __shared__ float4 AFh[2][BM/16][32];
    __shared__ float4 AFl[2][BM/16][32];
    __shared__ float2 BFh[2][16][32];
    __shared__ float2 BFl[2][16][32];

    int tid = threadIdx.x, lane = tid & 31, warp = tid >> 5;
    int bm = blockIdx.y * BM, bn = blockIdx.x * 128;
    int wmi = (warp & 1);                 // M half
    int wn  = (warp >> 1) * 32;
    int gid = lane >> 2, tig = lane & 3;

    // producer mapping
    int arow = (BM == 128) ? (tid >> 1) : (tid >> 1);   // BM=64: only tid<128 active
    int ak4  = (tid & 1) * 4;
    bool aact = (BM == 128) || (tid < 128);
    int al_ = 0, arb = 0, as_ = 0;
    if (aact){ arb = arow >> 4; al_ = (arow & 7)*4; as_ = ((arow >> 3) & 1) + 2*(tid & 1); }
    int bkr = tid >> 5, bn4 = (tid & 31) * 4;
    int bcb = bn4 >> 3, bl_ = (bn4 & 7)*4 + (bkr & 3), bs_ = bkr >> 2;

    const float* Aptr = A + (size_t)(bm + arow)*K + ak4;
    const float* Bptr = B + (size_t)bkr*N + bn + bn4;

    float acc[MT][4][4];
    #pragma unroll
    for (int i = 0; i < MT; i++)
        #pragma unroll
        for (int j = 0; j < 4; j++)
            #pragma unroll
            for (int e = 0; e < 4; e++) acc[i][j][e] = 0.f;

    // ---- producer store helper (k-slab -> buf) ----
    auto stage = [&](int buf, float4 av, float4 bv){
        if (aact){
            float a[4] = {av.x, av.y, av.z, av.w};
            #pragma unroll
            for (int i = 0; i < 4; i++){
                float h = tf32r(a[i]);
                ((float*)&AFh[buf][arb][al_ + i])[as_] = h;
                if (SPLIT) ((float*)&AFl[buf][arb][al_ + i])[as_] = tf32r(a[i] - h);
            }
        }
        float b[4] = {bv.x, bv.y, bv.z, bv.w};
        #pragma unroll
        for (int j = 0; j < 4; j++){
            float h = tf32r(b[j]);
            ((float*)&BFh[buf][bcb + (j >> 2)][bl_ + (j & 3)*4])[bs_] = h;   // j<4 so (j>>2)=0
            if (SPLIT) ((float*)&BFl[buf][bcb][bl_ + j*4])[bs_] = tf32r(b[j] - h);
        }
    };

    // prologue
    {
        float4 av = aact ? *(const float4*)Aptr : make_float4(0,0,0,0);
        float4 bv = *(const float4*)Bptr;
        stage(0, av, bv);
    }
    __syncthreads();

    int buf = 0;
    for (int k0 = 0; k0 < K; k0 += 8){
        bool more = (k0 + 8) < K;
        float4 av, bv;
        if (more){
            if (aact) av = *(const float4*)(Aptr + k0 + 8);
            bv = *(const float4*)(Bptr + (size_t)(k0 + 8)*N);
        }

        // load A fragments (hi & lo), one LDS.128 each
        uint4 ah[MT], al[MT];
        #pragma unroll
        for (int mt = 0; mt < MT; mt++){
            ah[mt] = *(const uint4*)&AFh[buf][wmi*MT + mt][lane];
            if (SPLIT) al[mt] = *(const uint4*)&AFl[buf][wmi*MT + mt][lane];
        }
        #pragma unroll
        for (int nt = 0; nt < 4; nt++){
            int cb = (wn >> 3) + nt;
            uint2 bh = *(const uint2*)&BFh[buf][cb][lane];
            uint2 bl;
            if (SPLIT) bl = *(const uint2*)&BFl[buf][cb][lane];
            #pragma unroll
            for (int mt = 0; mt < MT; mt++){
                if (SPLIT){
                    mma8(acc[mt][nt], (const unsigned*)&ah[mt], (const unsigned*)&bl);
                    mma8(acc[mt][nt], (const unsigned*)&al[mt], (const unsigned*)&bh);
                }
                mma8(acc[mt][nt], (const unsigned*)&ah[mt], (const unsigned*)&bh);
            }
        }

        if (more) stage(buf ^ 1, av, bv);
        __syncthreads();
        buf ^= 1;
    }

    // epilogue
    #pragma unroll
    for (int mt = 0; mt < MT; mt++){
        int row = bm + wmi*(BM/2) + mt*16 + gid;
        #pragma unroll
        for (int nt = 0; nt < 4; nt++){
            int col = bn + wn + nt*8 + tig*2;
            float b0 = bias ? bias[col]   : 0.f;
            float b1 = bias ? bias[col+1] : 0.f;
            float d0 = acc[mt][nt][0] + b0, d1 = acc[mt][nt][1] + b1;
            float d2 = acc[mt][nt][2] + b0, d3 = acc[mt][nt][3] + b1;
            if (relu){
                d0 = fmaxf(d0, 0.f); d1 = fmaxf(d1, 0.f);
                d2 = fmaxf(d2, 0.f); d3 = fmaxf(d3, 0.f);
            }
            *(float2*)(C + (size_t)row*N + col)     = make_float2(d0, d1);
            *(float2*)(C + (size_t)(row+8)*N + col) = make_float2(d2, d3);
        }
    }
}

// ---------------- gates: split-K partial GEMM (1024 x 48, K=2048) -------------
__global__ void gates_partial_kernel(const float* __restrict__ Wg){
    int ks = blockIdx.x;           // 0..15 -> K chunk of 128
    int bm = blockIdx.y * 128;
    int t = threadIdx.x;
    int rg = t >> 3, cg = t & 7;   // rows rg*4..+3, cols cg*6..+5
    __shared__ float s_a[128][17];
    __shared__ float s_b[16][48];
    float acc[4][6];
    #pragma unroll
    for (int i = 0; i < 4; i++)
        #pragma unroll
        for (int j = 0; j < 6; j++) acc[i][j] = 0.f;
    int k0base = ks * 128;
    for (int kk = 0; kk < 128; kk += 16){
        int row = t >> 1, kh = (t & 1) * 8;
        const float* src = g_xn + (size_t)(bm + row)*XDIM + k0base + kk + kh;
        float4 v0 = *(const float4*)src, v1 = *(const float4*)(src + 4);
        s_a[row][kh+0]=v0.x; s_a[row][kh+1]=v0.y; s_a[row][kh+2]=v0.z; s_a[row][kh+3]=v0.w;
        s_a[row][kh+4]=v1.x; s_a[row][kh+5]=v1.y; s_a[row][kh+6]=v1.z; s_a[row][kh+7]=v1.w;
        #pragma unroll
        for (int i = 0; i < 3; i++){
            int idx = i*256 + t;
            s_b[idx/48][idx%48] = Wg[(size_t)(k0base + kk + idx/48)*48 + idx%48];
        }
        __syncthreads();
        #pragma unroll 4
        for (int k = 0; k < 16; k++){
            float a[4], b[6];
            #pragma unroll
            for (int i = 0; i < 4; i++) a[i] = s_a[rg*4 + i][k];
            #pragma unroll
            for (int j = 0; j < 6; j++) b[j] = s_b[k][cg*6 + j];
            #pragma unroll
            for (int i = 0; i < 4; i++)
                #pragma unroll
                for (int j = 0; j < 6; j++) acc[i][j] += a[i]*b[j];
        }
        __syncthreads();
    }
    #pragma unroll
    for (int i = 0; i < 4; i++)
        #pragma unroll
        for (int j = 0; j < 6; j++)
            g_gpart[(size_t)ks*NSEQ*48 + (size_t)(bm + rg*4 + i)*48 + cg*6 + j] = acc[i][j];
}

// ---------------- build compressed-window MLP inputs ----------------
__global__ void build_windows_kernel(const float* __restrict__ k_pos,
                                     const float* __restrict__ v_pos){
    int idx = blockIdx.x * 256 + threadIdx.x;   // 2^20 total
    int d = idx & 127;
    int j = (idx >> 7) & 31;
    int w = (idx >> 12) & 63;
    int h = (idx >> 18) & 1;
    int s = (idx >> 19) & 1;
    int t = w*16 + j - 16;
    const float* pos = s ? v_pos : k_pos;
    float pv = pos[(h*32 + j)*128 + d];
    float val = 0.f;
    if (t >= 0) val = g_qkv[(size_t)t*QKVW + (s ? 2304 : 2048) + h*128 + d];
    g_f[(size_t)s*(128*CDIM) + (size_t)(h*64 + w)*CDIM + j*128 + d] = val + pv;
}

// ---------------- MLP2: 256 rows x 128 cols, K=4096 ----------------
__global__ void mlp2_kernel(const float* __restrict__ Wk2, const float* __restrict__ bk2,
                            const float* __restrict__ Wv2, const float* __restrict__ bv2){
    int r0 = blockIdx.x * 4;
    int c  = threadIdx.x;          // 0..127
    const float* B    = (r0 < 128) ? Wk2 : Wv2;
    const float* bias = (r0 < 128) ? bk2 : bv2;
    __shared__ __align__(16) float s_a[4][1024];
    float acc[4] = {0.f, 0.f, 0.f, 0.f};
    for (int kc = 0; kc < 4096; kc += 1024){
        #pragma unroll
        for (int i = 0; i < 8; i++){
            int idx = i*128 + threadIdx.x;  // float4 index 0..1023
            int rr = idx >> 8, cc = idx & 255;
            float4 v = *((const float4*)(g_hidden + (size_t)(r0 + rr)*4096 + kc) + cc);
            *((float4*)&s_a[rr][cc*4]) = v;
        }
        __syncthreads();
        #pragma unroll 4
        for (int k = 0; k < 1024; k++){
            float b = B[(size_t)(kc + k)*128 + c];
            acc[0] += s_a[0][k]*b; acc[1] += s_a[1][k]*b;
            acc[2] += s_a[2][k]*b; acc[3] += s_a[3][k]*b;
        }
        __syncthreads();
    }
    #pragma unroll
    for (int i = 0; i < 4; i++)
        g_ckv[(size_t)(r0 + i)*128 + c] = acc[i] + bias[c];
}

// ---------------- prepend mem_kv ----------------
__global__ void assemble_kernel(const float* __restrict__ mem_kv){
    int b = blockIdx.x;            // 0..259
    int d = threadIdx.x;           // 0..127
    int s = b / 130, hj = b % 130, h = hj / 65, j = hj % 65;
    float v;
    if (j == 0) v = mem_kv[(s*2 + h)*128 + d];
    else        v = g_ckv[(size_t)(s*128 + h*64 + (j-1))*128 + d];
    (s ? g_cvfull : g_ckfull)[(h*65 + j)*128 + d] = v;
}

// ---------------- compressed attention + importance + top-k selection ----------------
__global__ void cmp_attn_kernel(){
    int n = blockIdx.x, h = blockIdx.y;
    int warp = threadIdx.x >> 5, lane = threadIdx.x & 31;
    __shared__ float s_l[8][65];
    __shared__ float s_imp[16];

    const float* q = g_qkv + (size_t)n*QKVW + (h*GQH + warp)*DH;
    float4 qv = *(const float4*)(q + lane*4);

    #pragma unroll 4
    for (int j = 0; j < 65; j++){
        float4 kv = *(const float4*)(g_ckfull + (size_t)(h*65 + j)*DH + lane*4);
        float p = qv.x*kv.x + qv.y*kv.y + qv.z*kv.z + qv.w*kv.w;
        p = warp_sum(p);
        if (lane == 0) s_l[warp][j] = p * SCALE;
    }
    __syncthreads();

    if (threadIdx.x < 16){
        int f = threadIdx.x;
        float s = 0.f;
        #pragma unroll
        for (int g = 0; g < 8; g++)
            #pragma unroll
            for (int w = 0; w < 4; w++) s += s_l[g][1 + f*4 + w];
        s *= (1.f / 32.f);
        if ((n >> 6) == f) s = NEGBIG;
        s_imp[f] = s;
    }
    __syncthreads();

    if (threadIdx.x == 0){
        unsigned used = 0;
        int base = (h*NSEQ + n)*5;
        for (int r = 0; r < 4; r++){
            float best = -3.4e38f; int bi = 0;
            for (int f = 0; f < 16; f++)
                if (!((used >> f) & 1) && s_imp[f] > best){ best = s_imp[f]; bi = f; }
            used |= 1u << bi;
            g_sel[base + r] = bi;
        }
        g_sel[base + 4] = n >> 6;
    }

    float m = -3.4e38f;
    for (int j = lane; j < 65; j += 32) m = fmaxf(m, s_l[warp][j]);
    m = warp_max(m);
    float sum = 0.f;
    for (int j = lane; j < 65; j += 32){
        float e = __expf(s_l[warp][j] - m);
        s_l[warp][j] = e; sum += e;
    }
    sum = warp_sum(sum);
    float inv = 1.f / sum;

    float a0 = 0.f, a1 = 0.f, a2 = 0.f, a3 = 0.f;
    #pragma unroll 4
    for (int j = 0; j < 65; j++){
        float p = s_l[warp][j];
        float4 vv = *(const float4*)(g_cvfull + (size_t)(h*65 + j)*DH + lane*4);
        a0 += p*vv.x; a1 += p*vv.y; a2 += p*vv.z; a3 += p*vv.w;
    }
    float* o = g_cmp + ((size_t)(h*GQH + warp)*NSEQ + n)*DH + lane*4;
    o[0] = a0*inv; o[1] = a1*inv; o[2] = a2*inv; o[3] = a3*inv;
}

// ---------------- RoPE table (fp64) + apply ----------------
__global__ void ropetab_kernel(){
    int idx = blockIdx.x * 256 + threadIdx.x;    // 65536
    int i = idx & 63, n = idx >> 6;
    double f = exp(-((double)(2*i) / 128.0) * 9.210340371976184);
    double ang = (double)n * f;
    g_ropetab[idx*2 + 0] = (float)cos(ang);
    g_ropetab[idx*2 + 1] = (float)sin(ang);
}

__global__ void rope_kernel(){
    int n = blockIdx.x, hh = blockIdx.y, i = threadIdx.x;   // pair index 0..63
    float c = g_ropetab[(n*64 + i)*2 + 0];
    float s = g_ropetab[(n*64 + i)*2 + 1];
    const float* src; float* dst;
    if (hh < 16){
        src = g_qkv + (size_t)n*QKVW + hh*DH;
        dst = g_qrope + ((size_t)hh*NSEQ + n)*DH;
    } else {
        int h = hh - 16;
        src = g_qkv + (size_t)n*QKVW + 2048 + h*DH;
        dst = g_krope + ((size_t)h*NSEQ + n)*DH;
    }
    float x1 = src[2*i], x2 = src[2*i + 1];
    dst[2*i]     = x1*c - x2*s;
    dst[2*i + 1] = x1*s + x2*c;
}

// ---------------- fine (selected-block) attention ----------------
__global__ void fine_attn_kernel(){
    int n = blockIdx.x, h = blockIdx.y;
    int tid = threadIdx.x, warp = tid >> 5, lane = tid & 31;
    __shared__ __align__(16) float s_p[320][8];
    __shared__ int s_blk[5];
    if (tid < 5) s_blk[tid] = g_sel[(h*NSEQ + n)*5 + tid];
    __syncthreads();

    const float* q = g_qrope + ((size_t)(h*GQH + warp)*NSEQ + n)*DH;
    float4 qv = *(const float4*)(q + lane*4);

    for (int b = 0; b < 5; b++){
        int tok0 = s_blk[b] * 64;
        #pragma unroll 2
        for (int tt = 0; tt < 64; tt++){
            float4 kv = *(const float4*)(g_krope + ((size_t)h*NSEQ + tok0 + tt)*DH + lane*4);
            float p = qv.x*kv.x + qv.y*kv.y + qv.z*kv.z + qv.w*kv.w;
            p = warp_sum(p);
            if (lane == 0) s_p[b*64 + tt][warp] = p * SCALE;
        }
    }
    float m = -3.4e38f;
    for (int t = lane; t < 320; t += 32) m = fmaxf(m, s_p[t][warp]);
    m = warp_max(m);
    float sum = 0.f;
    for (int t = lane; t < 320; t += 32){
        float e = __expf(s_p[t][warp] - m);
        s_p[t][warp] = e; sum += e;
    }
    sum = warp_sum(sum);
    float inv = 1.f / sum;
    for (int t = lane; t < 320; t += 32) s_p[t][warp] *= inv;
    __syncthreads();

    int d = tid & 127, half = tid >> 7;
    float a[4] = {0.f, 0.f, 0.f, 0.f};
    for (int b = 0; b < 5; b++){
        size_t vbase = (size_t)s_blk[b]*64*QKVW + 2304 + h*DH + d;
        #pragma unroll 2
        for (int tt = 0; tt < 64; tt++){
            float v = g_qkv[vbase + (size_t)tt*QKVW];
            float4 p = *(const float4*)&s_p[b*64 + tt][half*4];
            a[0] += p.x*v; a[1] += p.y*v; a[2] += p.z*v; a[3] += p.w*v;
        }
    }
    #pragma unroll
    for (int gg = 0; gg < 4; gg++)
        g_fine[((size_t)(h*GQH + half*4 + gg)*NSEQ + n)*DH + d] = a[gg];
}

// ---------------- sliding-window attention (|dq-dk| <= 128) ----------------
__global__ void slide_attn_kernel(){
    int n = blockIdx.x, h = blockIdx.y;
    int tid = threadIdx.x, warp = tid >> 5, lane = tid & 31;
    __shared__ __align__(16) float s_p[257][8];
    int lo = n - 128; if (lo < 0) lo = 0;
    int hi = n + 128; if (hi > NSEQ - 1) hi = NSEQ - 1;
    int cnt = hi - lo + 1;

    const float* q = g_qrope + ((size_t)(h*GQH + warp)*NSEQ + n)*DH;
    float4 qv = *(const float4*)(q + lane*4);

    #pragma unroll 2
    for (int t = 0; t < cnt; t++){
        float4 kv = *(const float4*)(g_krope + ((size_t)h*NSEQ + lo + t)*DH + lane*4);
        float p = qv.x*kv.x + qv.y*kv.y + qv.z*kv.z + qv.w*kv.w;
        p = warp_sum(p);
        if (lane == 0) s_p[t][warp] = p * SCALE;
    }
    float m = -3.4e38f;
    for (int t = lane; t < cnt; t += 32) m = fmaxf(m, s_p[t][warp]);
    m = warp_max(m);
    float sum = 0.f;
    for (int t = lane; t < cnt; t += 32){
        float e = __expf(s_p[t][warp] - m);
        s_p[t][warp] = e; sum += e;
    }
    sum = warp_sum(sum);
    float inv = 1.f / sum;
    for (int t = lane; t < cnt; t += 32) s_p[t][warp] *= inv;
    __syncthreads();

    int d = tid & 127, half = tid >> 7;
    float a[4] = {0.f, 0.f, 0.f, 0.f};
    size_t vbase = (size_t)lo*QKVW + 2304 + h*DH + d;
    #pragma unroll 2
    for (int t = 0; t < cnt; t++){
        float v = g_qkv[vbase + (size_t)t*QKVW];
        float4 p = *(const float4*)&s_p[t][half*4];
        a[0] += p.x*v; a[1] += p.y*v; a[2] += p.z*v; a[3] += p.w*v;
    }
    #pragma unroll
    for (int gg = 0; gg < 4; gg++)
        g_slide[((size_t)(h*GQH + half*4 + gg)*NSEQ + n)*DH + d] = a[gg];
}

// ---------------- gate-weighted combine (sums split-K gate partials) ----------
__global__ void combine_kernel(const float* __restrict__ bg){
    int n = blockIdx.x, hq = blockIdx.y, d = threadIdx.x;
    __shared__ float sg[3];
    if (d < 3){
        float s = bg[hq*3 + d];
        #pragma unroll
        for (int p = 0; p < 16; p++)
            s += g_gpart[(size_t)p*NSEQ*48 + (size_t)n*48 + hq*3 + d];
        sg[d] = 1.f / (1.f + __expf(-s));
    }
    __syncthreads();
    float g0 = sg[0], g1 = sg[1], g2 = sg[2];
    size_t idx = ((size_t)hq*NSEQ + n)*DH + d;
    g_O1[(size_t)n*XDIM + hq*DH + d] =
        g_cmp[idx]*g0 + g_fine[idx]*g1 + g_slide[idx]*g2;
}

// ---------------- launch ----------------
extern "C" void kernel_launch(void* const* d_in, const int* in_sizes, int n_in,
                              void* d_out, int out_size){
    const float* x      = (const float*)d_in[0];
    const float* g_norm = (const float*)d_in[1];
    const float* W_qkv  = (const float*)d_in[2];
    const float* k_pos  = (const float*)d_in[3];
    const float* v_pos  = (const float*)d_in[4];
    const float* mem_kv = (const float*)d_in[5];
    const float* Wk1    = (const float*)d_in[6];
    const float* bk1    = (const float*)d_in[7];
    const float* Wk2    = (const float*)d_in[8];
    const float* bk2    = (const float*)d_in[9];
    const float* Wv1    = (const float*)d_in[10];
    const float* bv1    = (const float*)d_in[11];
    const float* Wv2    = (const float*)d_in[12];
    const float* bv2    = (const float*)d_in[13];
    const float* Wg     = (const float*)d_in[14];
    const float* bg     = (const float*)d_in[15];
    const float* W_out  = (const float*)d_in[16];
    float* out = (float*)d_out;

    float *p_xn, *p_qkv, *p_f, *p_hidden, *p_O1;
    cudaGetSymbolAddress((void**)&p_xn,     g_xn);
    cudaGetSymbolAddress((void**)&p_qkv,    g_qkv);
    cudaGetSymbolAddress((void**)&p_f,      g_f);
    cudaGetSymbolAddress((void**)&p_hidden, g_hidden);
    cudaGetSymbolAddress((void**)&p_O1,     g_O1);

    rmsnorm_kernel<<<NSEQ, 256>>>(x, g_norm);                 // 0
    ropetab_kernel<<<256, 256>>>();                            // 1
    gates_partial_kernel<<<dim3(16, NSEQ/128), 256>>>(Wg);     // 2

    // 3 (ncu-captured): qkv = xn @ W_qkv : 1024 x 2560 x 2048 (3xTF32)
    tf32_gemm_frag<128, true><<<dim3(QKVW/128, NSEQ/128, 1), 256>>>(
        p_xn, W_qkv, W_qkv, nullptr, nullptr, p_qkv,
        NSEQ, QKVW, XDIM, 0, 0, 0);

    build_windows_kernel<<<4096, 256>>>(k_pos, v_pos);         // 4

    // MLP1 (k & v batched): relu(f @ W1 + b1) : (128 x 4096 x 4096) x2 (3xTF32, BM=64)
    tf32_gemm_frag<64, true><<<dim3(CDIM/128, 2, 2), 256>>>(
        p_f, Wk1, Wv1, bk1, bv1, p_hidden,
        128, CDIM, CDIM, 1, (size_t)128*CDIM, (size_t)128*CDIM);

    mlp2_kernel<<<64, 128>>>(Wk2, bk2, Wv2, bv2);
    assemble_kernel<<<260, 128>>>(mem_kv);

    cmp_attn_kernel<<<dim3(NSEQ, KVH), 256>>>();
    rope_kernel<<<dim3(NSEQ, 18), 64>>>();
    fine_attn_kernel<<<dim3(NSEQ, KVH), 256>>>();
    slide_attn_kernel<<<dim3(NSEQ, KVH), 256>>>();

    combine_kernel<<<dim3(NSEQ, NHEADS), 128>>>(bg);

    // out = O1 @ W_out : 1024 x 2048 x 2048 (plain TF32 — after all decisions)
    tf32_gemm_frag<128, false><<<dim3(XDIM/128, NSEQ/128, 1), 256>>>(
        p_O1, W_out, W_out, nullptr, nullptr, out,
        NSEQ, XDIM, XDIM, 0, 0, 0);
}

// round 5
// speedup vs baseline: 1.8844x; 1.8844x over previous
#include <cuda_runtime.h>
#include <math.h>
#include <stdint.h>

#define NSEQ   1024
#define XDIM   2048
#define NHEADS 16
#define KVH    2
#define GQH    8
#define DH     128
#define QKVW   2560      // 2048 + 256 + 256
#define CDIM   4096      // CMP_BLK * DH
#define SCALE  0.08838834764831845f
#define NEGBIG -1e10f

// ---------------- scratch (device globals; no runtime allocation) ----------------
__device__ __align__(128) float g_xn    [NSEQ*XDIM];
__device__ __align__(128) float g_qkv   [NSEQ*QKVW];
__device__ __align__(128) float g_hidden[2*128*CDIM];
__device__ __align__(128) float g_ckv   [256*DH];
__device__ __align__(128) float g_ckfull[KVH*65*DH];
__device__ __align__(128) float g_cvfull[KVH*65*DH];
__device__ __align__(128) float g_cmp   [NHEADS*NSEQ*DH];
__device__ __align__(128) float g_fine  [NHEADS*NSEQ*DH];
__device__ __align__(128) float g_slide [NHEADS*NSEQ*DH];
__device__ __align__(128) float g_qrope [NHEADS*NSEQ*DH];
__device__ __align__(128) float g_krope [KVH*NSEQ*DH];
__device__ __align__(128) float g_ropetab[NSEQ*64*2];
__device__ __align__(128) float g_gpart [16*NSEQ*48];
__device__ int g_sel[KVH*NSEQ*5];

// fragment-layout operand buffers
// B frag: [K/8][N/8][32] float4 {bh(k),bh(k+4),bl(k),bl(k+4)} at lane (n&7)*4+(k&3)
__device__ float4 g_BFq[256*320*32];        // W_qkv
__device__ float4 g_BF1[2*512*512*32];      // Wk1, Wv1
__device__ float4 g_BFo[256*256*32];        // W_out
// A frag: [K/8][M/16][32] float4 slots = ((m>>3)&1)+2*((k>>2)&1), lane (m&7)*4+(k&3)
__device__ float4 g_AXh[256*64*32],  g_AXl[256*64*32];    // xn
__device__ float4 g_AFh[2*512*8*32], g_AFl[2*512*8*32];   // compress-MLP inputs
__device__ float4 g_AOh[256*64*32],  g_AOl[256*64*32];    // combined O1

// ---------------- helpers ----------------
__device__ __forceinline__ float warp_sum(float v){
    #pragma unroll
    for (int o = 16; o > 0; o >>= 1) v += __shfl_xor_sync(0xffffffffu, v, o);
    return v;
}
__device__ __forceinline__ float warp_max(float v){
    #pragma unroll
    for (int o = 16; o > 0; o >>= 1) v = fmaxf(v, __shfl_xor_sync(0xffffffffu, v, o));
    return v;
}
__device__ __forceinline__ float tf32r(float x){
    unsigned r; asm("cvt.rna.tf32.f32 %0, %1;" : "=r"(r) : "f"(x));
    return __uint_as_float(r);
}
__device__ __forceinline__ void mma8(float* d, const unsigned* a, const unsigned* b){
    asm volatile("mma.sync.aligned.m16n8k8.row.col.f32.tf32.tf32.f32 "
        "{%0,%1,%2,%3},{%4,%5,%6,%7},{%8,%9},{%0,%1,%2,%3};"
        : "+f"(d[0]),"+f"(d[1]),"+f"(d[2]),"+f"(d[3])
        : "r"(a[0]),"r"(a[1]),"r"(a[2]),"r"(a[3]),"r"(b[0]),"r"(b[1]));
}
__device__ __forceinline__ void cp16(uint32_t s, const void* g){
    asm volatile("cp.async.cg.shared.global [%0], [%1], 16;" :: "r"(s), "l"(g));
}
// store one value into A-frag arrays (hi & lo) given (row, k)
__device__ __forceinline__ void afrag_store(float* ph, float* pl, int M16,
                                            int row, int k, float v){
    int ks = k >> 3, mt = row >> 4;
    int lane = (row & 7)*4 + (k & 3);
    int slot = ((row >> 3) & 1) + 2*((k >> 2) & 1);
    size_t fi = (((size_t)ks*M16 + mt)*32 + lane)*4 + slot;
    float h = tf32r(v);
    ph[fi] = h;
    pl[fi] = tf32r(v - h);
}

// ---------------- rmsnorm (also emits xn A-frag split) ----------------
__global__ void rmsnorm_kernel(const float* __restrict__ x, const float* __restrict__ g){
    int n = blockIdx.x, tid = threadIdx.x;
    const float4* row = (const float4*)(x + (size_t)n*XDIM);
    float s = 0.f;
    for (int i = tid; i < XDIM/4; i += 256){
        float4 v = row[i];
        s += v.x*v.x + v.y*v.y + v.z*v.z + v.w*v.w;
    }
    s = warp_sum(s);
    __shared__ float red[8];
    __shared__ float tot;
    if ((tid & 31) == 0) red[tid >> 5] = s;
    __syncthreads();
    if (tid < 32){
        float v = (tid < 8) ? red[tid] : 0.f;
        v = warp_sum(v);
        if (tid == 0) tot = rsqrtf(v / (float)XDIM + 1e-6f);
    }
    __syncthreads();
    float inv = tot;
    const float4* gg = (const float4*)g;
    float4* op = (float4*)(g_xn + (size_t)n*XDIM);
    float* ph = (float*)g_AXh;
    float* pl = (float*)g_AXl;
    for (int i = tid; i < XDIM/4; i += 256){
        float4 v = row[i], w = gg[i], o;
        o.x = v.x*inv*w.x; o.y = v.y*inv*w.y; o.z = v.z*inv*w.z; o.w = v.w*inv*w.w;
        op[i] = o;
        int k0 = i*4;
        afrag_store(ph, pl, 64, n, k0+0, o.x);
        afrag_store(ph, pl, 64, n, k0+1, o.y);
        afrag_store(ph, pl, 64, n, k0+2, o.z);
        afrag_store(ph, pl, 64, n, k0+3, o.w);
    }
}

// ---------------- weight prep: W[K][N] -> B-frag packed float4 ----------------
__global__ void prep_w(const float* __restrict__ W, float4* __restrict__ BF,
                       int N, int K){
    int n0 = blockIdx.x*64, k0 = blockIdx.y*64;
    __shared__ float sw[64][65];
    int t = threadIdx.x;
    #pragma unroll
    for (int ii = 0; ii < 4; ii++){
        int r = ii*16 + (t >> 4), c4 = (t & 15)*4;
        float4 v = *(const float4*)(W + (size_t)(k0 + r)*N + n0 + c4);
        sw[r][c4+0]=v.x; sw[r][c4+1]=v.y; sw[r][c4+2]=v.z; sw[r][c4+3]=v.w;
    }
    __syncthreads();
    int lane = t & 31, ct = t >> 5;
    int c = lane & 3, gcol = lane >> 2;
    #pragma unroll
    for (int i = 0; i < 8; i++){
        float v1 = sw[i*8 + c][ct*8 + gcol];
        float v2 = sw[i*8 + 4 + c][ct*8 + gcol];
        float h1 = tf32r(v1), l1 = tf32r(v1 - h1);
        float h2 = tf32r(v2), l2 = tf32r(v2 - h2);
        BF[((size_t)(k0/8 + i)*(N >> 3) + (n0 >> 3) + ct)*32 + lane] =
            make_float4(h1, h2, l1, l2);
    }
}

// ---------------- tensor-core GEMM (3xTF32), frag operands in gmem ----------------
// BN=64, BK=32, 8 warps. BM=128: warps 4(M)x2(N), NT=4. BM=64: 2(M)x4(N), NT=2.
template<int BM>
__global__ __launch_bounds__(256)
void gemm_tc(const float4* __restrict__ AFh, const float4* __restrict__ AFl,
             const float4* __restrict__ BF,
             const float* __restrict__ bias0, const float* __restrict__ bias1,
             float* __restrict__ C,
             int M16, int N, int K, int relu,
             size_t sAf4, size_t sBf4, size_t sC){
    constexpr int MT16 = BM/16;
    constexpr int WM = (BM == 128) ? 4 : 2;
    constexpr int WN = 8/WM;
    constexpr int NT = 64/(WN*8);
    constexpr int SA_STAGE = 2*4*MT16*32;   // f4 per stage (hi+lo)
    constexpr int SB_STAGE = 4*8*32;
    constexpr int IA = (2*4*MT16*32)/256;

    extern __shared__ float4 smem[];
    float4* sB = smem + 2*SA_STAGE;

    const float* bias = blockIdx.z ? bias1 : bias0;
    AFh += blockIdx.z*sAf4; AFl += blockIdx.z*sAf4; BF += blockIdx.z*sBf4;
    C += blockIdx.z*sC;

    int tid = threadIdx.x, lane = tid & 31, warp = tid >> 5;
    int bm16 = blockIdx.y*MT16;
    int bn8  = blockIdx.x*8;
    int wmi = warp % WM, wni = warp / WM;
    int gid = lane >> 2, tig = lane & 3;
    int N8 = N >> 3;

    uint32_t sbase = (uint32_t)__cvta_generic_to_shared(smem);

    float acc[2][NT][4];
    #pragma unroll
    for (int i = 0; i < 2; i++)
        #pragma unroll
        for (int j = 0; j < NT; j++)
            #pragma unroll
            for (int e = 0; e < 4; e++) acc[i][j][e] = 0.f;

    auto issue = [&](int ksl, int buf){
        #pragma unroll
        for (int i = 0; i < IA; i++){
            int idx = i*256 + tid;
            int l = idx & 31, q = idx >> 5;
            int mt = q % MT16, ks = (q/MT16) & 3, a = q/(MT16*4);
            const float4* src = (a ? AFl : AFh)
                + ((size_t)(ksl*4 + ks)*M16 + bm16 + mt)*32 + l;
            uint32_t dst = sbase + (uint32_t)(((((buf*2)+a)*4+ks)*MT16+mt)*32+l)*16u;
            cp16(dst, src);
        }
        #pragma unroll
        for (int i = 0; i < 4; i++){
            int idx = i*256 + tid;
            int l = idx & 31, ct = (idx >> 5) & 7, ks = idx >> 8;
            const float4* src = BF + ((size_t)(ksl*4 + ks)*N8 + bn8 + ct)*32 + l;
            uint32_t dst = sbase + (uint32_t)(2*SA_STAGE + ((buf*4+ks)*8+ct)*32 + l)*16u;
            cp16(dst, src);
        }
        asm volatile("cp.async.commit_group;");
    };

    int nslab = K/32;
    issue(0, 0);
    int buf = 0;
    for (int ksl = 0; ksl < nslab; ksl++){
        asm volatile("cp.async.wait_group 0;");
        __syncthreads();
        if (ksl + 1 < nslab) issue(ksl + 1, buf ^ 1);
        #pragma unroll
        for (int ks = 0; ks < 4; ks++){
            uint4 ah[2], al[2];
            #pragma unroll
            for (int mt = 0; mt < 2; mt++){
                int mtt = wmi*2 + mt;
                ah[mt] = *(const uint4*)&smem[(((buf*2+0)*4+ks)*MT16+mtt)*32 + lane];
                al[mt] = *(const uint4*)&smem[(((buf*2+1)*4+ks)*MT16+mtt)*32 + lane];
            }
            #pragma unroll
            for (int nt = 0; nt < NT; nt++){
                float4 bf = sB[((buf*4+ks)*8 + wni*NT + nt)*32 + lane];
                unsigned bh[2] = {__float_as_uint(bf.x), __float_as_uint(bf.y)};
                unsigned bl[2] = {__float_as_uint(bf.z), __float_as_uint(bf.w)};
                #pragma unroll
                for (int mt = 0; mt < 2; mt++){
                    mma8(acc[mt][nt], (const unsigned*)&ah[mt], bl);
                    mma8(acc[mt][nt], (const unsigned*)&al[mt], bh);
                    mma8(acc[mt][nt], (const unsigned*)&ah[mt], bh);
                }
            }
        }
        buf ^= 1;
    }

    #pragma unroll
    for (int mt = 0; mt < 2; mt++){
        int row = (bm16 + wmi*2 + mt)*16 + gid;
        #pragma unroll
        for (int nt = 0; nt < NT; nt++){
            int col = (bn8 + wni*NT + nt)*8 + tig*2;
            float b0 = bias ? bias[col]   : 0.f;
            float b1 = bias ? bias[col+1] : 0.f;
            float d0 = acc[mt][nt][0] + b0, d1 = acc[mt][nt][1] + b1;
            float d2 = acc[mt][nt][2] + b0, d3 = acc[mt][nt][3] + b1;
            if (relu){
                d0 = fmaxf(d0, 0.f); d1 = fmaxf(d1, 0.f);
                d2 = fmaxf(d2, 0.f); d3 = fmaxf(d3, 0.f);
            }
            *(float2*)(C + (size_t)row*N + col)     = make_float2(d0, d1);
            *(float2*)(C + (size_t)(row+8)*N + col) = make_float2(d2, d3);
        }
    }
}

// ---------------- gates: split-K partial GEMM (1024 x 48, K=2048) -------------
__global__ void gates_partial_kernel(const float* __restrict__ Wg){
    int ks = blockIdx.x;
    int bm = blockIdx.y * 128;
    int t = threadIdx.x;
    int rg = t >> 3, cg = t & 7;
    __shared__ float s_a[128][17];
    __shared__ float s_b[16][48];
    float acc[4][6];
    #pragma unroll
    for (int i = 0; i < 4; i++)
        #pragma unroll
        for (int j = 0; j < 6; j++) acc[i][j] = 0.f;
    int k0base = ks * 128;
    for (int kk = 0; kk < 128; kk += 16){
        int row = t >> 1, kh = (t & 1) * 8;
        const float* src = g_xn + (size_t)(bm + row)*XDIM + k0base + kk + kh;
        float4 v0 = *(const float4*)src, v1 = *(const float4*)(src + 4);
        s_a[row][kh+0]=v0.x; s_a[row][kh+1]=v0.y; s_a[row][kh+2]=v0.z; s_a[row][kh+3]=v0.w;
        s_a[row][kh+4]=v1.x; s_a[row][kh+5]=v1.y; s_a[row][kh+6]=v1.z; s_a[row][kh+7]=v1.w;
        #pragma unroll
        for (int i = 0; i < 3; i++){
            int idx = i*256 + t;
            s_b[idx/48][idx%48] = Wg[(size_t)(k0base + kk + idx/48)*48 + idx%48];
        }
        __syncthreads();
        #pragma unroll 4
        for (int k = 0; k < 16; k++){
            float a[4], b[6];
            #pragma unroll
            for (int i = 0; i < 4; i++) a[i] = s_a[rg*4 + i][k];
            #pragma unroll
            for (int j = 0; j < 6; j++) b[j] = s_b[k][cg*6 + j];
            #pragma unroll
            for (int i = 0; i < 4; i++)
                #pragma unroll
                for (int j = 0; j < 6; j++) acc[i][j] += a[i]*b[j];
        }
        __syncthreads();
    }
    #pragma unroll
    for (int i = 0; i < 4; i++)
        #pragma unroll
        for (int j = 0; j < 6; j++)
            g_gpart[(size_t)ks*NSEQ*48 + (size_t)(bm + rg*4 + i)*48 + cg*6 + j] = acc[i][j];
}

// ---------------- build compressed-window MLP inputs (direct to A-frag) -------
__global__ void build_windows_kernel(const float* __restrict__ k_pos,
                                     const float* __restrict__ v_pos){
    int idx = blockIdx.x * 256 + threadIdx.x;   // 2^20 total
    int d = idx & 127;
    int j = (idx >> 7) & 31;
    int w = (idx >> 12) & 63;
    int h = (idx >> 18) & 1;
    int s = (idx >> 19) & 1;
    int t = w*16 + j - 16;
    const float* pos = s ? v_pos : k_pos;
    float pv = pos[(h*32 + j)*128 + d];
    float val = 0.f;
    if (t >= 0) val = g_qkv[(size_t)t*QKVW + (s ? 2304 : 2048) + h*128 + d];
    float v = val + pv;
    int row = h*64 + w;            // 0..127
    int k   = j*128 + d;           // 0..4095
    float* ph = (float*)(g_AFh + (size_t)s*512*8*32);
    float* pl = (float*)(g_AFl + (size_t)s*512*8*32);
    afrag_store(ph, pl, 8, row, k, v);
}

// ---------------- MLP2: 256 rows x 128 cols, K=4096 ----------------
__global__ void mlp2_kernel(const float* __restrict__ Wk2, const float* __restrict__ bk2,
                            const float* __restrict__ Wv2, const float* __restrict__ bv2){
    int r0 = blockIdx.x * 4;
    int c  = threadIdx.x;
    const float* B    = (r0 < 128) ? Wk2 : Wv2;
    const float* bias = (r0 < 128) ? bk2 : bv2;
    __shared__ __align__(16) float s_a[4][1024];
    float acc[4] = {0.f, 0.f, 0.f, 0.f};
    for (int kc = 0; kc < 4096; kc += 1024){
        #pragma unroll
        for (int i = 0; i < 8; i++){
            int idx = i*128 + threadIdx.x;
            int rr = idx >> 8, cc = idx & 255;
            float4 v = *((const float4*)(g_hidden + (size_t)(r0 + rr)*4096 + kc) + cc);
            *((float4*)&s_a[rr][cc*4]) = v;
        }
        __syncthreads();
        #pragma unroll 4
        for (int k = 0; k < 1024; k++){
            float b = B[(size_t)(kc + k)*128 + c];
            acc[0] += s_a[0][k]*b; acc[1] += s_a[1][k]*b;
            acc[2] += s_a[2][k]*b; acc[3] += s_a[3][k]*b;
        }
        __syncthreads();
    }
    #pragma unroll
    for (int i = 0; i < 4; i++)
        g_ckv[(size_t)(r0 + i)*128 + c] = acc[i] + bias[c];
}

// ---------------- prepend mem_kv ----------------
__global__ void assemble_kernel(const float* __restrict__ mem_kv){
    int b = blockIdx.x;
    int d = threadIdx.x;
    int s = b / 130, hj = b % 130, h = hj / 65, j = hj % 65;
    float v;
    if (j == 0) v = mem_kv[(s*2 + h)*128 + d];
    else        v = g_ckv[(size_t)(s*128 + h*64 + (j-1))*128 + d];
    (s ? g_cvfull : g_ckfull)[(h*65 + j)*128 + d] = v;
}

// ---------------- compressed attention + importance + top-k selection ----------------
__global__ void cmp_attn_kernel(){
    int n = blockIdx.x, h = blockIdx.y;
    int warp = threadIdx.x >> 5, lane = threadIdx.x & 31;
    __shared__ float s_l[8][65];
    __shared__ float s_imp[16];

    const float* q = g_qkv + (size_t)n*QKVW + (h*GQH + warp)*DH;
    float4 qv = *(const float4*)(q + lane*4);

    #pragma unroll 4
    for (int j = 0; j < 65; j++){
        float4 kv = *(const float4*)(g_ckfull + (size_t)(h*65 + j)*DH + lane*4);
        float p = qv.x*kv.x + qv.y*kv.y + qv.z*kv.z + qv.w*kv.w;
        p = warp_sum(p);
        if (lane == 0) s_l[warp][j] = p * SCALE;
    }
    __syncthreads();

    if (threadIdx.x < 16){
        int f = threadIdx.x;
        float s = 0.f;
        #pragma unroll
        for (int g = 0; g < 8; g++)
            #pragma unroll
            for (int w = 0; w < 4; w++) s += s_l[g][1 + f*4 + w];
        s *= (1.f / 32.f);
        if ((n >> 6) == f) s = NEGBIG;
        s_imp[f] = s;
    }
    __syncthreads();

    if (threadIdx.x == 0){
        unsigned used = 0;
        int base = (h*NSEQ + n)*5;
        for (int r = 0; r < 4; r++){
            float best = -3.4e38f; int bi = 0;
            for (int f = 0; f < 16; f++)
                if (!((used >> f) & 1) && s_imp[f] > best){ best = s_imp[f]; bi = f; }
            used |= 1u << bi;
            g_sel[base + r] = bi;
        }
        g_sel[base + 4] = n >> 6;
    }

    float m = -3.4e38f;
    for (int j = lane; j < 65; j += 32) m = fmaxf(m, s_l[warp][j]);
    m = warp_max(m);
    float sum = 0.f;
    for (int j = lane; j < 65; j += 32){
        float e = __expf(s_l[warp][j] - m);
        s_l[warp][j] = e; sum += e;
    }
    sum = warp_sum(sum);
    float inv = 1.f / sum;

    float a0 = 0.f, a1 = 0.f, a2 = 0.f, a3 = 0.f;
    #pragma unroll 4
    for (int j = 0; j < 65; j++){
        float p = s_l[warp][j];
        float4 vv = *(const float4*)(g_cvfull + (size_t)(h*65 + j)*DH + lane*4);
        a0 += p*vv.x; a1 += p*vv.y; a2 += p*vv.z; a3 += p*vv.w;
    }
    float* o = g_cmp + ((size_t)(h*GQH + warp)*NSEQ + n)*DH + lane*4;
    o[0] = a0*inv; o[1] = a1*inv; o[2] = a2*inv; o[3] = a3*inv;
}

// ---------------- RoPE table (fp64) + apply ----------------
__global__ void ropetab_kernel(){
    int idx = blockIdx.x * 256 + threadIdx.x;
    int i = idx & 63, n = idx >> 6;
    double f = exp(-((double)(2*i) / 128.0) * 9.210340371976184);
    double ang = (double)n * f;
    g_ropetab[idx*2 + 0] = (float)cos(ang);
    g_ropetab[idx*2 + 1] = (float)sin(ang);
}

__global__ void rope_kernel(){
    int n = blockIdx.x, hh = blockIdx.y, i = threadIdx.x;
    float c = g_ropetab[(n*64 + i)*2 + 0];
    float s = g_ropetab[(n*64 + i)*2 + 1];
    const float* src; float* dst;
    if (hh < 16){
        src = g_qkv + (size_t)n*QKVW + hh*DH;
        dst = g_qrope + ((size_t)hh*NSEQ + n)*DH;
    } else {
        int h = hh - 16;
        src = g_qkv + (size_t)n*QKVW + 2048 + h*DH;
        dst = g_krope + ((size_t)h*NSEQ + n)*DH;
    }
    float x1 = src[2*i], x2 = src[2*i + 1];
    dst[2*i]     = x1*c - x2*s;
    dst[2*i + 1] = x1*s + x2*c;
}

// ---------------- fine (selected-block) attention ----------------
__global__ void fine_attn_kernel(){
    int n = blockIdx.x, h = blockIdx.y;
    int tid = threadIdx.x, warp = tid >> 5, lane = tid & 31;
    __shared__ __align__(16) float s_p[320][8];
    __shared__ int s_blk[5];
    if (tid < 5) s_blk[tid] = g_sel[(h*NSEQ + n)*5 + tid];
    __syncthreads();

    const float* q = g_qrope + ((size_t)(h*GQH + warp)*NSEQ + n)*DH;
    float4 qv = *(const float4*)(q + lane*4);

    for (int b = 0; b < 5; b++){
        int tok0 = s_blk[b] * 64;
        #pragma unroll 2
        for (int tt = 0; tt < 64; tt++){
            float4 kv = *(const float4*)(g_krope + ((size_t)h*NSEQ + tok0 + tt)*DH + lane*4);
            float p = qv.x*kv.x + qv.y*kv.y + qv.z*kv.z + qv.w*kv.w;
            p = warp_sum(p);
            if (lane == 0) s_p[b*64 + tt][warp] = p * SCALE;
        }
    }
    float m = -3.4e38f;
    for (int t = lane; t < 320; t += 32) m = fmaxf(m, s_p[t][warp]);
    m = warp_max(m);
    float sum = 0.f;
    for (int t = lane; t < 320; t += 32){
        float e = __expf(s_p[t][warp] - m);
        s_p[t][warp] = e; sum += e;
    }
    sum = warp_sum(sum);
    float inv = 1.f / sum;
    for (int t = lane; t < 320; t += 32) s_p[t][warp] *= inv;
    __syncthreads();

    int d = tid & 127, half = tid >> 7;
    float a[4] = {0.f, 0.f, 0.f, 0.f};
    for (int b = 0; b < 5; b++){
        size_t vbase = (size_t)s_blk[b]*64*QKVW + 2304 + h*DH + d;
        #pragma unroll 2
        for (int tt = 0; tt < 64; tt++){
            float v = g_qkv[vbase + (size_t)tt*QKVW];
            float4 p = *(const float4*)&s_p[b*64 + tt][half*4];
            a[0] += p.x*v; a[1] += p.y*v; a[2] += p.z*v; a[3] += p.w*v;
        }
    }
    #pragma unroll
    for (int gg = 0; gg < 4; gg++)
        g_fine[((size_t)(h*GQH + half*4 + gg)*NSEQ + n)*DH + d] = a[gg];
}

// ---------------- sliding-window attention (|dq-dk| <= 128) ----------------
__global__ void slide_attn_kernel(){
    int n = blockIdx.x, h = blockIdx.y;
    int tid = threadIdx.x, warp = tid >> 5, lane = tid & 31;
    __shared__ __align__(16) float s_p[257][8];
    int lo = n - 128; if (lo < 0) lo = 0;
    int hi = n + 128; if (hi > NSEQ - 1) hi = NSEQ - 1;
    int cnt = hi - lo + 1;

    const float* q = g_qrope + ((size_t)(h*GQH + warp)*NSEQ + n)*DH;
    float4 qv = *(const float4*)(q + lane*4);

    #pragma unroll 2
    for (int t = 0; t < cnt; t++){
        float4 kv = *(const float4*)(g_krope + ((size_t)h*NSEQ + lo + t)*DH + lane*4);
        float p = qv.x*kv.x + qv.y*kv.y + qv.z*kv.z + qv.w*kv.w;
        p = warp_sum(p);
        if (lane == 0) s_p[t][warp] = p * SCALE;
    }
    float m = -3.4e38f;
    for (int t = lane; t < cnt; t += 32) m = fmaxf(m, s_p[t][warp]);
    m = warp_max(m);
    float sum = 0.f;
    for (int t = lane; t < cnt; t += 32){
        float e = __expf(s_p[t][warp] - m);
        s_p[t][warp] = e; sum += e;
    }
    sum = warp_sum(sum);
    float inv = 1.f / sum;
    for (int t = lane; t < cnt; t += 32) s_p[t][warp] *= inv;
    __syncthreads();

    int d = tid & 127, half = tid >> 7;
    float a[4] = {0.f, 0.f, 0.f, 0.f};
    size_t vbase = (size_t)lo*QKVW + 2304 + h*DH + d;
    #pragma unroll 2
    for (int t = 0; t < cnt; t++){
        float v = g_qkv[vbase + (size_t)t*QKVW];
        float4 p = *(const float4*)&s_p[t][half*4];
        a[0] += p.x*v; a[1] += p.y*v; a[2] += p.z*v; a[3] += p.w*v;
    }
    #pragma unroll
    for (int gg = 0; gg < 4; gg++)
        g_slide[((size_t)(h*GQH + half*4 + gg)*NSEQ + n)*DH + d] = a[gg];
}

// ---------------- gate-weighted combine -> O1 A-frag split ----------------
__global__ void combine_kernel(const float* __restrict__ bg){
    int n = blockIdx.x, hq = blockIdx.y, d = threadIdx.x;
    __shared__ float sg[3];
    if (d < 3){
        float s = bg[hq*3 + d];
        #pragma unroll
        for (int p = 0; p < 16; p++)
            s += g_gpart[(size_t)p*NSEQ*48 + (size_t)n*48 + hq*3 + d];
        sg[d] = 1.f / (1.f + __expf(-s));
    }
    __syncthreads();
    float g0 = sg[0], g1 = sg[1], g2 = sg[2];
    size_t idx = ((size_t)hq*NSEQ + n)*DH + d;
    float o = g_cmp[idx]*g0 + g_fine[idx]*g1 + g_slide[idx]*g2;
    afrag_store((float*)g_AOh, (float*)g_AOl, 64, n, hq*128 + d, o);
}

// ---------------- launch ----------------
extern "C" void kernel_launch(void* const* d_in, const int* in_sizes, int n_in,
                              void* d_out, int out_size){
    const float* x      = (const float*)d_in[0];
    const float* g_norm = (const float*)d_in[1];
    const float* W_qkv  = (const float*)d_in[2];
    const float* k_pos  = (const float*)d_in[3];
    const float* v_pos  = (const float*)d_in[4];
    const float* mem_kv = (const float*)d_in[5];
    const float* Wk1    = (const float*)d_in[6];
    const float* bk1    = (const float*)d_in[7];
    const float* Wk2    = (const float*)d_in[8];
    const float* bk2    = (const float*)d_in[9];
    const float* Wv1    = (const float*)d_in[10];
    const float* bv1    = (const float*)d_in[11];
    const float* Wv2    = (const float*)d_in[12];
    const float* bv2    = (const float*)d_in[13];
    const float* Wg     = (const float*)d_in[14];
    const float* bg     = (const float*)d_in[15];
    const float* W_out  = (const float*)d_in[16];
    float* out = (float*)d_out;

    cudaFuncSetAttribute(gemm_tc<128>, cudaFuncAttributeMaxDynamicSharedMemorySize, 98304);
    cudaFuncSetAttribute(gemm_tc<64>,  cudaFuncAttributeMaxDynamicSharedMemorySize, 65536);

    float4 *p_BFq, *p_BF1, *p_BFo, *p_AXh, *p_AXl, *p_AFh, *p_AFl, *p_AOh, *p_AOl;
    float *p_qkv, *p_hidden;
    cudaGetSymbolAddress((void**)&p_BFq, g_BFq);
    cudaGetSymbolAddress((void**)&p_BF1, g_BF1);
    cudaGetSymbolAddress((void**)&p_BFo, g_BFo);
    cudaGetSymbolAddress((void**)&p_AXh, g_AXh);
    cudaGetSymbolAddress((void**)&p_AXl, g_AXl);
    cudaGetSymbolAddress((void**)&p_AFh, g_AFh);
    cudaGetSymbolAddress((void**)&p_AFl, g_AFl);
    cudaGetSymbolAddress((void**)&p_AOh, g_AOh);
    cudaGetSymbolAddress((void**)&p_AOl, g_AOl);
    cudaGetSymbolAddress((void**)&p_qkv, g_qkv);
    cudaGetSymbolAddress((void**)&p_hidden, g_hidden);

    prep_w<<<dim3(QKVW/64, XDIM/64), 256>>>(W_qkv, p_BFq, QKVW, XDIM);   // 0
    rmsnorm_kernel<<<NSEQ, 256>>>(x, g_norm);                             // 1
    ropetab_kernel<<<256, 256>>>();                                       // 2

    // 3 (ncu-captured): qkv = xn @ W_qkv : 1024 x 2560 x 2048
    gemm_tc<128><<<dim3(QKVW/64, NSEQ/128, 1), 256, 98304>>>(
        p_AXh, p_AXl, p_BFq, nullptr, nullptr, p_qkv,
        64, QKVW, XDIM, 0, 0, 0, 0);

    gates_partial_kernel<<<dim3(16, NSEQ/128), 256>>>(Wg);                // 4
    prep_w<<<dim3(CDIM/64, CDIM/64), 256>>>(Wk1, p_BF1, CDIM, CDIM);      // 5
    prep_w<<<dim3(CDIM/64, CDIM/64), 256>>>(Wv1, p_BF1 + (size_t)512*512*32, CDIM, CDIM); // 6
    build_windows_kernel<<<4096, 256>>>(k_pos, v_pos);                    // 7

    // MLP1 (k & v batched): relu(f @ W1 + b1) : (128 x 4096 x 4096) x2
    gemm_tc<64><<<dim3(CDIM/64, 2, 2), 256, 65536>>>(
        p_AFh, p_AFl, p_BF1, bk1, bv1, p_hidden,
        8, CDIM, CDIM, 1,
        (size_t)512*8*32, (size_t)512*512*32, (size_t)128*CDIM);

    mlp2_kernel<<<64, 128>>>(Wk2, bk2, Wv2, bv2);
    assemble_kernel<<<260, 128>>>(mem_kv);

    cmp_attn_kernel<<<dim3(NSEQ, KVH), 256>>>();
    rope_kernel<<<dim3(NSEQ, 18), 64>>>();
    fine_attn_kernel<<<dim3(NSEQ, KVH), 256>>>();
    slide_attn_kernel<<<dim3(NSEQ, KVH), 256>>>();

    prep_w<<<dim3(XDIM/64, XDIM/64), 256>>>(W_out, p_BFo, XDIM, XDIM);
    combine_kernel<<<dim3(NSEQ, NHEADS), 128>>>(bg);

    // out = O1 @ W_out : 1024 x 2048 x 2048
    gemm_tc<128><<<dim3(XDIM/64, NSEQ/128, 1), 256, 98304>>>(
        p_AOh, p_AOl, p_BFo, nullptr, nullptr, out,
        64, XDIM, XDIM, 0, 0, 0, 0);
}